// round 1
// baseline (speedup 1.0000x reference)
#include <cuda_runtime.h>
#include <cuda_bf16.h>

#define NBINS    65536
#define CAP      4096
#define MAXC     300
#define TOPN     100
#define MAXN     1000448

// ---- scratch (device globals: no allocations allowed) ----
__device__ float              g_scores[MAXN];
__device__ unsigned int       g_hist[NBINS];
__device__ unsigned int       g_count;
__device__ int                g_thrbin;
__device__ unsigned long long g_cand[CAP];

// ---------------- shared box decode ----------------
__device__ __forceinline__ void decode_box(
    const float* __restrict__ bbox, const float* __restrict__ rois,
    int i, int a, float W, float H,
    float& bx1, float& by1, float& bx2, float& by2)
{
    float x1 = rois[(size_t)i*5+1];
    float y1 = rois[(size_t)i*5+2];
    float x2 = rois[(size_t)i*5+3];
    float y2 = rois[(size_t)i*5+4];
    float w  = x2 - x1 + 1.0f;
    float h  = y2 - y1 + 1.0f;
    float cx = x1 + 0.5f*(w - 1.0f);
    float cy = y1 + 0.5f*(h - 1.0f);
    // row*20 + a*4 floats -> 16-byte aligned
    float4 d = *reinterpret_cast<const float4*>(bbox + (size_t)i*20 + a*4);
    float dx = d.x*0.1f, dy = d.y*0.1f, dw = d.z*0.2f, dh = d.w*0.2f;
    float pcx = dx*w + cx;
    float pcy = dy*h + cy;
    float pw  = expf(dw)*w;
    float ph  = expf(dh)*h;
    bx1 = fminf(fmaxf(pcx - 0.5f*(pw - 1.0f), 0.0f), W);
    by1 = fminf(fmaxf(pcy - 0.5f*(ph - 1.0f), 0.0f), H);
    bx2 = fminf(fmaxf(pcx + 0.5f*(pw - 1.0f), 0.0f), W);
    by2 = fminf(fmaxf(pcy + 0.5f*(ph - 1.0f), 0.0f), H);
}

// ---------------- K0: reset scratch ----------------
__global__ void k0_zero() {
    int i = blockIdx.x*blockDim.x + threadIdx.x;
    if (i < NBINS) g_hist[i] = 0u;
    if (i == 0) { g_count = 0u; g_thrbin = 0; }
}

// ---------------- K1: per-roi score + histogram ----------------
__global__ void k1_score(const float* __restrict__ cls,
                         const float* __restrict__ bbox,
                         const float* __restrict__ rois,
                         const float* __restrict__ iminfo,
                         int n)
{
    int i = blockIdx.x*blockDim.x + threadIdx.x;
    if (i >= n) return;
    const float* c = cls + (size_t)i*5;
    float s0 = c[0], s1 = c[1], s2 = c[2], s3 = c[3], s4 = c[4];
    float m = s1; int a = 1;
    if (s2 > m) { m = s2; a = 2; }
    if (s3 > m) { m = s3; a = 3; }
    if (s4 > m) { m = s4; a = 4; }
    float score = -1.0f;
    if ((1.0f - s0 >= 0.2f) && (m > 0.1f)) {
        float W = iminfo[1] - 1.0f, H = iminfo[0] - 1.0f;
        float bx1, by1, bx2, by2;
        decode_box(bbox, rois, i, a, W, H, bx1, by1, bx2, by2);
        float bw = bx2 - bx1 + 1.0f;
        float bh = by2 - by1 + 1.0f;
        if (bw >= 6.0f || bh >= 6.0f) {
            score = m;
            int bin = (int)(m * 65536.0f);
            bin = min(max(bin, 0), NBINS - 1);
            atomicAdd(&g_hist[bin], 1u);
        }
    }
    g_scores[i] = score;
}

// ---------------- K2: find threshold bin (top-300) ----------------
__global__ void k2_thresh() {
    __shared__ unsigned int part[1024];
    int t = threadIdx.x;
    unsigned int s = 0;
    int base = t * (NBINS/1024);
    #pragma unroll 8
    for (int b = 0; b < NBINS/1024; b++) s += g_hist[base + b];
    part[t] = s;
    __syncthreads();
    if (t == 0) {
        unsigned int cum = 0;
        int thr = 0;
        int chunk = -1;
        for (int cch = 1023; cch >= 0; --cch) {
            if (cum + part[cch] >= (unsigned)MAXC) { chunk = cch; break; }
            cum += part[cch];
        }
        if (chunk >= 0) {
            int lo = chunk * (NBINS/1024);
            thr = lo;
            for (int b = lo + (NBINS/1024) - 1; b >= lo; --b) {
                cum += g_hist[b];
                if (cum >= (unsigned)MAXC) { thr = b; break; }
            }
        }
        g_thrbin = thr;
    }
}

// ---------------- K3: collect candidates above threshold ----------------
__global__ void k3_collect(int n) {
    int i = blockIdx.x*blockDim.x + threadIdx.x;
    if (i >= n) return;
    float s = g_scores[i];
    if (s < 0.0f) return;
    int bin = (int)(s * 65536.0f);
    bin = min(max(bin, 0), NBINS - 1);
    if (bin < g_thrbin) return;
    unsigned int pos = atomicAdd(&g_count, 1u);
    if (pos < CAP) {
        // key: ascending sort => (score desc, idx asc). score>0 so bits monotone.
        unsigned long long key =
            ((unsigned long long)(~__float_as_uint(s)) << 32) | (unsigned int)i;
        g_cand[pos] = key;
    }
}

// ---------------- K4: sort + decode + NMS + output ----------------
__global__ void k4_final(const float* __restrict__ cls,
                         const float* __restrict__ bbox,
                         const float* __restrict__ rois,
                         const float* __restrict__ iminfo,
                         float* __restrict__ out)
{
    __shared__ unsigned long long keys[CAP];   // reused as suppression bitmatrix later
    __shared__ float bx[MAXC][4];
    __shared__ float pr[MAXC][5];
    __shared__ float area[MAXC];
    __shared__ int   kept[TOPN];
    __shared__ int   nkept;

    int tid = threadIdx.x;
    int M = (int)min(g_count, (unsigned int)CAP);

    // pad to power of two
    int S = 2; while (S < M) S <<= 1;
    for (int t = tid; t < S; t += blockDim.x)
        keys[t] = (t < M) ? g_cand[t] : 0xFFFFFFFFFFFFFFFFULL;
    __syncthreads();

    // bitonic ascending sort
    for (int k = 2; k <= S; k <<= 1) {
        for (int j = k >> 1; j > 0; j >>= 1) {
            for (int t = tid; t < S; t += blockDim.x) {
                int p = t ^ j;
                if (p > t) {
                    unsigned long long a = keys[t];
                    unsigned long long b = keys[p];
                    bool up = ((t & k) == 0);
                    if ((a > b) == up) { keys[t] = b; keys[p] = a; }
                }
            }
            __syncthreads();
        }
    }

    int K = min(M, MAXC);
    float W = iminfo[1] - 1.0f, H = iminfo[0] - 1.0f;

    // decode top-K candidates
    for (int t = tid; t < K; t += blockDim.x) {
        int i = (int)(unsigned int)(keys[t] & 0xFFFFFFFFULL);
        const float* c = cls + (size_t)i*5;
        float c0=c[0], c1=c[1], c2=c[2], c3=c[3], c4=c[4];
        pr[t][0]=c0; pr[t][1]=c1; pr[t][2]=c2; pr[t][3]=c3; pr[t][4]=c4;
        float m = c1; int a = 1;
        if (c2 > m) { m = c2; a = 2; }
        if (c3 > m) { m = c3; a = 3; }
        if (c4 > m) { m = c4; a = 4; }
        float bx1, by1, bx2, by2;
        decode_box(bbox, rois, i, a, W, H, bx1, by1, bx2, by2);
        bx[t][0]=bx1; bx[t][1]=by1; bx[t][2]=bx2; bx[t][3]=by2;
        area[t] = (bx2 - bx1) * (by2 - by1);
    }
    __syncthreads();

    // suppression bitmatrix (reuse keys storage): rm[i][w] bit b => iou(i, w*64+b)>0.5, j>i
    unsigned long long* rm = keys;
    const int NW = (MAXC + 63) / 64;  // 5
    for (int task = tid; task < K * NW; task += blockDim.x) {
        int i = task / NW;
        int w = task % NW;
        float ax1=bx[i][0], ay1=bx[i][1], ax2=bx[i][2], ay2=bx[i][3], aa=area[i];
        unsigned long long bits = 0ULL;
        int j0 = w * 64;
        int jend = min(j0 + 64, K);
        for (int j = max(j0, i+1); j < jend; j++) {
            float lx = fmaxf(ax1, bx[j][0]);
            float ly = fmaxf(ay1, bx[j][1]);
            float rx = fminf(ax2, bx[j][2]);
            float ry = fminf(ay2, bx[j][3]);
            float iw = fmaxf(rx - lx, 0.0f);
            float ih = fmaxf(ry - ly, 0.0f);
            float inter = iw * ih;
            float iou = inter / (aa + area[j] - inter);
            if (iou > 0.5f) bits |= 1ULL << (j - j0);
        }
        rm[i*NW + w] = bits;
    }
    __syncthreads();

    // serial greedy walk (exactly JAX fori_loop semantics)
    if (tid == 0) {
        unsigned long long sup[NW];
        #pragma unroll
        for (int w = 0; w < NW; w++) sup[w] = 0ULL;
        int cnt = 0;
        for (int i = 0; i < K && cnt < TOPN; i++) {
            if (!((sup[i >> 6] >> (i & 63)) & 1ULL)) {
                kept[cnt++] = i;
                #pragma unroll
                for (int w = 0; w < NW; w++) sup[w] |= rm[i*NW + w];
            }
        }
        nkept = cnt;
    }
    __syncthreads();

    // zero output then scatter kept rows
    for (int t = tid; t < TOPN*10; t += blockDim.x) out[t] = 0.0f;
    __syncthreads();
    int nk = nkept;
    for (int r = tid; r < nk; r += blockDim.x) {
        int i = kept[r];
        float* o = out + r*10;
        o[0] = 0.0f;
        o[1] = bx[i][0]; o[2] = bx[i][1]; o[3] = bx[i][2]; o[4] = bx[i][3];
        o[5] = pr[i][0]; o[6] = pr[i][1]; o[7] = pr[i][2]; o[8] = pr[i][3]; o[9] = pr[i][4];
    }
}

// ---------------- launch ----------------
extern "C" void kernel_launch(void* const* d_in, const int* in_sizes, int n_in,
                              void* d_out, int out_size)
{
    const float* cls    = (const float*)d_in[0];
    const float* bbox   = (const float*)d_in[1];
    const float* rois   = (const float*)d_in[2];
    const float* iminfo = (const float*)d_in[3];
    float* out = (float*)d_out;
    int n = in_sizes[0] / 5;
    if (n > MAXN) n = MAXN;

    k0_zero  <<<(NBINS + 255)/256, 256>>>();
    k1_score <<<(n + 255)/256, 256>>>(cls, bbox, rois, iminfo, n);
    k2_thresh<<<1, 1024>>>();
    k3_collect<<<(n + 255)/256, 256>>>(n);
    k4_final <<<1, 1024>>>(cls, bbox, rois, iminfo, out);
}